// round 5
// baseline (speedup 1.0000x reference)
#include <cuda_runtime.h>
#include <math.h>

// Problem constants
#define BB 128
#define NN 2000
#define CC 100
#define DD 128
#define HH 8
#define DKK 16
#define NEGV (-1000000000.0f)
#define CLIPV 10.0f

// Output layout (float32, flattened tuple order)
// aug:      [0,        65536)   B*512
// guid_emb: [65536,    81920)   B*128
// guidance: [81920,    82048)   B
// clu_prob: [82048,    94848)   B*100
#define OUT_AUG 0
#define OUT_GEMB 65536
#define OUT_GUID 81920
#define OUT_CLU 82048

// Shared memory layout (float offsets). All float4 regions are 16B aligned.
#define S_CS 0           // cluster tile [100][129]
#define S_WB 12900       // weight stage / reduction scratch [128][129]
#define S_M1 29412       // mean1 [128]
#define S_M2 29540       // mean2 [128]
#define S_CUR 29668      // current [128]
#define S_DEP 29796      // depot [128]
#define S_CTX 29924      // context [384]
#define S_QV 30308       // q [128]
#define S_QH 30436       // qh [128]
#define S_R4 30564       // r packed [128][8]
#define S_U4 31588       // u packed [128][8]
#define S_SC 32612       // scores [8][104]
#define S_AT4 33444      // attn packed [100][8]
#define S_WS4 34244      // wsum packed [128][8]
#define S_YS 35268       // y [8][132]
#define S_GV 36324       // glimpse (pre-Wmo) [128]
#define S_GO 36452       // glimpse @ Wmo [128]
#define S_GW 36580       // Wks @ go [128]
#define S_PART 36708     // logit partials [100][2] (pad 208)
#define S_LGT 36916      // logits [104]
#define S_MISC 37020     // [0]=gid [1]=max+lse
#define S_VCM 37036      // vcm [104]
#define SMEM_FLOATS 37140
#define SMEM_BYTES (SMEM_FLOATS * 4)

__device__ __forceinline__ bool rdmask(const void* p, int flag, long long i) {
    if (flag == 0) return ((const unsigned char*)p)[i] != 0;
    if (flag == 1) return ((const int*)p)[i] != 0;
    return ((const float*)p)[i] != 0.0f;
}

// Masked-mean accumulation over node_embeddings, specialized on mask dtype.
template <int F>
__device__ __forceinline__ void means_acc(const float* __restrict__ np_,
                                          const void* __restrict__ maskp,
                                          const void* __restrict__ cmaskp,
                                          long long mbase, int w, int d0,
                                          float4& a1, float4& a2) {
#pragma unroll 5
    for (int n = w; n < NN; n += 8) {
        float4 v = *(const float4*)(np_ + (size_t)n * DD + d0);
        bool m, cmv;
        if (F == 0) {
            m = ((const unsigned char*)maskp)[mbase + n] != 0;
            cmv = ((const unsigned char*)cmaskp)[mbase + n] != 0;
        } else if (F == 1) {
            m = ((const int*)maskp)[mbase + n] != 0;
            cmv = ((const int*)cmaskp)[mbase + n] != 0;
        } else {
            m = ((const float*)maskp)[mbase + n] != 0.0f;
            cmv = ((const float*)cmaskp)[mbase + n] != 0.0f;
        }
        bool mc = m | cmv;
        if (!m)  { a1.x += v.x; a1.y += v.y; a1.z += v.z; a1.w += v.w; }
        if (!mc) { a2.x += v.x; a2.y += v.y; a2.z += v.z; a2.w += v.w; }
    }
}

__global__ void __launch_bounds__(256, 1)
clu_fused_kernel(const float* __restrict__ depot, const float* __restrict__ cluster,
                 const float* __restrict__ curE, const float* __restrict__ node,
                 const void* __restrict__ isnewp, const void* __restrict__ cmaskp,
                 const void* __restrict__ vcmp, const void* __restrict__ maskp,
                 const float* __restrict__ Wq, const float* __restrict__ Wk,
                 const float* __restrict__ Wv, const float* __restrict__ Wks,
                 const float* __restrict__ Wmq, const float* __restrict__ Wmk,
                 const float* __restrict__ Wmv, const float* __restrict__ Wmo,
                 float* __restrict__ out) {
    extern __shared__ float sm[];
    const int b = blockIdx.x;
    const int t = threadIdx.x;
    const int lane = t & 31;
    const int w = t >> 5;

    // ---- Phase 0a: sniff bool serialization dtype (byte / int32 / float32) ----
    unsigned wword = ((const unsigned*)maskp)[t];  // first 1024 bytes of `mask`
    int o1  = __syncthreads_or((wword & 0x0000ff00u) ? 1 : 0);
    int o23 = __syncthreads_or((wword & 0xffff0000u) ? 1 : 0);
    const int flag = o1 ? 0 : (o23 ? 2 : 1);

    // ---- Phase 0b: small loads (current/depot/vcm), cluster tile -> smem ----
    if (t < DD) {
        sm[S_CUR + t] = curE[b * DD + t];
        sm[S_DEP + t] = depot[b * DD + t];
    }
    if (t < CC) sm[S_VCM + t] = rdmask(vcmp, flag, (long long)b * CC + t) ? 1.0f : 0.0f;
    const bool isnew = rdmask(isnewp, flag, b);

    {
        const float* cp = cluster + (size_t)b * CC * DD;
        for (int p4 = t; p4 < (CC * DD) / 4; p4 += 256) {
            float4 v = ((const float4*)cp)[p4];
            int base = p4 * 4;
            float* dst = sm + S_CS + (base >> 7) * 129 + (base & 127);
            dst[0] = v.x; dst[1] = v.y; dst[2] = v.z; dst[3] = v.w;
        }
    }
    __syncthreads();

    // vcm[0] adjustment: all_vis over c=1..99 (warp 0)
    if (w == 0) {
        bool ok = true;
        for (int c = 1 + lane; c < CC; c += 32) ok = ok && (sm[S_VCM + c] != 0.0f);
        bool allv = __all_sync(0xffffffffu, ok);
        if (lane == 0 && isnew) sm[S_VCM + 0] = allv ? 0.0f : 1.0f;
    }

    // ---- Phase 1: masked means over node_embeddings (the HBM pass) ----
    {
        const float* np_ = node + (size_t)b * NN * DD;
        const long long mbase = (long long)b * NN;
        const int d0 = lane * 4;
        float4 a1 = make_float4(0.f, 0.f, 0.f, 0.f);
        float4 a2 = make_float4(0.f, 0.f, 0.f, 0.f);
        if (flag == 0)      means_acc<0>(np_, maskp, cmaskp, mbase, w, d0, a1, a2);
        else if (flag == 1) means_acc<1>(np_, maskp, cmaskp, mbase, w, d0, a1, a2);
        else                means_acc<2>(np_, maskp, cmaskp, mbase, w, d0, a1, a2);
        // deterministic cross-warp reduction via Wb scratch
        float* red1 = sm + S_WB;
        float* red2 = sm + S_WB + 1024;
        int o = w * 128 + d0;
        red1[o] = a1.x; red1[o + 1] = a1.y; red1[o + 2] = a1.z; red1[o + 3] = a1.w;
        red2[o] = a2.x; red2[o + 1] = a2.y; red2[o + 2] = a2.z; red2[o + 3] = a2.w;
    }
    __syncthreads();
    if (t < DD) {
        float s1 = 0.f, s2 = 0.f;
#pragma unroll
        for (int ww = 0; ww < 8; ww++) {
            s1 += sm[S_WB + ww * 128 + t];
            s2 += sm[S_WB + 1024 + ww * 128 + t];
        }
        float m1 = s1 * (1.0f / NN), m2 = s2 * (1.0f / NN);
        sm[S_M1 + t] = m1;
        sm[S_M2 + t] = m2;
        sm[S_CTX + t] = m1;
        sm[S_CTX + 128 + t] = sm[S_CUR + t];
        sm[S_CTX + 256 + t] = sm[S_DEP + t];
    }
    __syncthreads();

    // ---- Phase 2: q = ctx @ Wq ; qh = q @ Wmq ----
    if (t < DD) {
        float acc = 0.f;
#pragma unroll 8
        for (int i = 0; i < 3 * DD; i++) acc = fmaf(sm[S_CTX + i], Wq[i * DD + t], acc);
        sm[S_QV + t] = acc;
    }
    __syncthreads();
    if (t < DD) {
        float acc = 0.f;
#pragma unroll 8
        for (int j = 0; j < DD; j++) acc = fmaf(sm[S_QV + j], Wmq[j * DD + t], acc);
        sm[S_QH + t] = acc;
    }
    __syncthreads();

    // ---- Phase 3: stage Wmk; r[h][j] = sum_k Wmk[j][16h+k]*qh[16h+k] ----
    for (int p4 = t; p4 < (DD * DD) / 4; p4 += 256) {
        float4 v = ((const float4*)Wmk)[p4];
        int base = p4 * 4;
        float* dst = sm + S_WB + (base >> 7) * 129 + (base & 127);
        dst[0] = v.x; dst[1] = v.y; dst[2] = v.z; dst[3] = v.w;
    }
    __syncthreads();
    {
        int j = t & 127, par = t >> 7;
        float racc[4];
#pragma unroll
        for (int m = 0; m < 4; m++) {
            int h = par + 2 * m;
            float a = 0.f;
#pragma unroll
            for (int k = 0; k < 16; k++)
                a = fmaf(sm[S_WB + j * 129 + 16 * h + k], sm[S_QH + 16 * h + k], a);
            racc[m] = a;
        }
        float* dst = sm + S_R4 + j * 8 + par * 4;
        dst[0] = racc[0]; dst[1] = racc[1]; dst[2] = racc[2]; dst[3] = racc[3];
    }
    __syncthreads();

    // ---- Phase 4: stage Wk; u[h][i] = sum_j Wk[i][j]*r[h][j] ----
    for (int p4 = t; p4 < (DD * DD) / 4; p4 += 256) {
        float4 v = ((const float4*)Wk)[p4];
        int base = p4 * 4;
        float* dst = sm + S_WB + (base >> 7) * 129 + (base & 127);
        dst[0] = v.x; dst[1] = v.y; dst[2] = v.z; dst[3] = v.w;
    }
    __syncthreads();
    {
        int i = t & 127, par = t >> 7;
        float acc[4] = {0.f, 0.f, 0.f, 0.f};
#pragma unroll 4
        for (int j = 0; j < DD; j++) {
            float wv_ = sm[S_WB + i * 129 + j];
            float4 rv = *(const float4*)(sm + S_R4 + j * 8 + par * 4);
            acc[0] = fmaf(wv_, rv.x, acc[0]);
            acc[1] = fmaf(wv_, rv.y, acc[1]);
            acc[2] = fmaf(wv_, rv.z, acc[2]);
            acc[3] = fmaf(wv_, rv.w, acc[3]);
        }
        float* dst = sm + S_U4 + i * 8 + par * 4;
        dst[0] = acc[0]; dst[1] = acc[1]; dst[2] = acc[2]; dst[3] = acc[3];
    }
    __syncthreads();

    // ---- Phase 5: scores[c][h] = cluster[c]·u[h] * 0.25, masked ----
    if (t < 2 * CC) {
        int c = t >> 1, par = t & 1;
        float acc[4] = {0.f, 0.f, 0.f, 0.f};
#pragma unroll 4
        for (int i = 0; i < DD; i++) {
            float cv = sm[S_CS + c * 129 + i];
            float4 uu = *(const float4*)(sm + S_U4 + i * 8 + par * 4);
            acc[0] = fmaf(cv, uu.x, acc[0]);
            acc[1] = fmaf(cv, uu.y, acc[1]);
            acc[2] = fmaf(cv, uu.z, acc[2]);
            acc[3] = fmaf(cv, uu.w, acc[3]);
        }
        bool msk = sm[S_VCM + c] != 0.0f;
#pragma unroll
        for (int m = 0; m < 4; m++) {
            int h = par + 2 * m;
            sm[S_SC + h * 104 + c] = msk ? NEGV : acc[m] * 0.25f;
        }
    }
    __syncthreads();

    // ---- Phase 5b: softmax over c, per head (warp h) ----
    {
        int h = w;
        float mx = -INFINITY;
        for (int c = lane; c < CC; c += 32) mx = fmaxf(mx, sm[S_SC + h * 104 + c]);
#pragma unroll
        for (int off = 16; off; off >>= 1) mx = fmaxf(mx, __shfl_xor_sync(0xffffffffu, mx, off));
        float s = 0.f;
        for (int c = lane; c < CC; c += 32) {
            float e = expf(sm[S_SC + h * 104 + c] - mx);
            s += e;
            sm[S_AT4 + c * 8 + (h & 1) * 4 + (h >> 1)] = e;
        }
#pragma unroll
        for (int off = 16; off; off >>= 1) s += __shfl_xor_sync(0xffffffffu, s, off);
        float inv = 1.0f / s;
        for (int c = lane; c < CC; c += 32)
            sm[S_AT4 + c * 8 + (h & 1) * 4 + (h >> 1)] *= inv;
    }
    __syncthreads();

    // ---- Phase 6: wsum[h][i] = sum_c attn[h][c]*cluster[c][i] ----
    {
        int i = t & 127, par = t >> 7;
        float acc[4] = {0.f, 0.f, 0.f, 0.f};
#pragma unroll 4
        for (int c = 0; c < CC; c++) {
            float cv = sm[S_CS + c * 129 + i];
            float4 av = *(const float4*)(sm + S_AT4 + c * 8 + par * 4);
            acc[0] = fmaf(av.x, cv, acc[0]);
            acc[1] = fmaf(av.y, cv, acc[1]);
            acc[2] = fmaf(av.z, cv, acc[2]);
            acc[3] = fmaf(av.w, cv, acc[3]);
        }
        float* dst = sm + S_WS4 + i * 8 + par * 4;
        dst[0] = acc[0]; dst[1] = acc[1]; dst[2] = acc[2]; dst[3] = acc[3];
    }
    __syncthreads();

    // ---- Phase 7: y[h][j] = sum_i wsum[h][i]*Wv[i][j] ----
    {
        int j = t & 127, par = t >> 7;
        float acc[4] = {0.f, 0.f, 0.f, 0.f};
#pragma unroll 4
        for (int i = 0; i < DD; i++) {
            float wvv = Wv[i * DD + j];
            float4 sv = *(const float4*)(sm + S_WS4 + i * 8 + par * 4);
            acc[0] = fmaf(sv.x, wvv, acc[0]);
            acc[1] = fmaf(sv.y, wvv, acc[1]);
            acc[2] = fmaf(sv.z, wvv, acc[2]);
            acc[3] = fmaf(sv.w, wvv, acc[3]);
        }
#pragma unroll
        for (int m = 0; m < 4; m++) sm[S_YS + (par + 2 * m) * 132 + j] = acc[m];
    }
    __syncthreads();

    // ---- Phase 7b: glimpse[16h+k] = sum_j y[h][j]*Wmv[j][16h+k]; then @Wmo ----
    if (t < DD) {
        int h = t >> 4;
        float acc = 0.f;
#pragma unroll 8
        for (int j = 0; j < DD; j++) acc = fmaf(sm[S_YS + h * 132 + j], Wmv[j * DD + t], acc);
        sm[S_GV + t] = acc;
    }
    __syncthreads();
    if (t < DD) {
        float acc = 0.f;
#pragma unroll 8
        for (int j = 0; j < DD; j++) acc = fmaf(sm[S_GV + j], Wmo[j * DD + t], acc);
        sm[S_GO + t] = acc;
    }
    __syncthreads();

    // ---- Phase 8: stage Wks; gw[i] = sum_j Wks[i][j]*go[j]; logits ----
    for (int p4 = t; p4 < (DD * DD) / 4; p4 += 256) {
        float4 v = ((const float4*)Wks)[p4];
        int base = p4 * 4;
        float* dst = sm + S_WB + (base >> 7) * 129 + (base & 127);
        dst[0] = v.x; dst[1] = v.y; dst[2] = v.z; dst[3] = v.w;
    }
    __syncthreads();
    if (t < DD) {
        float acc = 0.f;
#pragma unroll 8
        for (int j = 0; j < DD; j++) acc = fmaf(sm[S_WB + t * 129 + j], sm[S_GO + j], acc);
        sm[S_GW + t] = acc;
    }
    __syncthreads();
    if (t < 2 * CC) {
        int c = t >> 1, half = t & 1;
        float acc = 0.f;
        int i0 = half * 64;
#pragma unroll 8
        for (int i = i0; i < i0 + 64; i++)
            acc = fmaf(sm[S_CS + c * 129 + i], sm[S_GW + i], acc);
        sm[S_PART + c * 2 + half] = acc;
    }
    __syncthreads();
    if (t < CC) {
        float lg = (sm[S_PART + t * 2] + sm[S_PART + t * 2 + 1]) * 0.08838834764831845f;
        lg = tanhf(lg) * CLIPV;
        sm[S_LGT + t] = (sm[S_VCM + t] != 0.0f) ? NEGV : lg;
    }
    __syncthreads();

    // ---- Phase 8b: argmax (first-index ties) + logsumexp (warp 0) ----
    if (w == 0) {
        float bv = -INFINITY;
        int bi = 0x7fffffff;
        for (int c = lane; c < CC; c += 32) {
            float v = sm[S_LGT + c];
            if (v > bv || (v == bv && c < bi)) { bv = v; bi = c; }
        }
#pragma unroll
        for (int off = 16; off; off >>= 1) {
            float ov = __shfl_down_sync(0xffffffffu, bv, off);
            int oi = __shfl_down_sync(0xffffffffu, bi, off);
            if (ov > bv || (ov == bv && oi < bi)) { bv = ov; bi = oi; }
        }
        bv = __shfl_sync(0xffffffffu, bv, 0);
        bi = __shfl_sync(0xffffffffu, bi, 0);
        float s = 0.f;
        for (int c = lane; c < CC; c += 32) s += expf(sm[S_LGT + c] - bv);
#pragma unroll
        for (int off = 16; off; off >>= 1) s += __shfl_xor_sync(0xffffffffu, s, off);
        if (lane == 0) {
            sm[S_MISC + 0] = (float)bi;
            sm[S_MISC + 1] = bv + logf(s);
        }
    }
    __syncthreads();

    // ---- Phase 9: outputs ----
    const int gid = (int)sm[S_MISC + 0];
    const float mlse = sm[S_MISC + 1];
    float* aug = out + OUT_AUG + (size_t)b * 512;
    float* gout = out + OUT_GEMB + (size_t)b * 128;
    float* cpo = out + OUT_CLU + (size_t)b * CC;
    if (t < DD) {
        float ge = sm[S_CS + gid * 129 + t];
        aug[t]        = isnew ? sm[S_M2 + t] : 0.0f;
        aug[128 + t]  = isnew ? sm[S_CUR + t] : 0.0f;
        aug[256 + t]  = isnew ? ge : 0.0f;
        aug[384 + t]  = isnew ? sm[S_DEP + t] : 0.0f;
        gout[t]       = isnew ? ge : 0.0f;
    }
    if (t < CC) cpo[t] = isnew ? (sm[S_LGT + t] - mlse) : 0.0f;
    if (t == 0) out[OUT_GUID + b] = isnew ? (float)gid : 0.0f;
}

extern "C" void kernel_launch(void* const* d_in, const int* in_sizes, int n_in,
                              void* d_out, int out_size) {
    (void)in_sizes; (void)n_in; (void)out_size;
    const float* depot   = (const float*)d_in[0];
    const float* cluster = (const float*)d_in[1];
    const float* curE    = (const float*)d_in[2];
    const float* node    = (const float*)d_in[3];
    const void*  isnewp  = d_in[4];
    const void*  cmaskp  = d_in[5];
    const void*  vcmp    = d_in[6];
    const void*  maskp   = d_in[7];
    const float* Wq  = (const float*)d_in[8];
    const float* Wk  = (const float*)d_in[9];
    const float* Wv  = (const float*)d_in[10];
    const float* Wks = (const float*)d_in[11];
    const float* Wmq = (const float*)d_in[12];
    const float* Wmk = (const float*)d_in[13];
    const float* Wmv = (const float*)d_in[14];
    const float* Wmo = (const float*)d_in[15];

    cudaFuncSetAttribute(clu_fused_kernel,
                         cudaFuncAttributeMaxDynamicSharedMemorySize, SMEM_BYTES);
    clu_fused_kernel<<<BB, 256, SMEM_BYTES>>>(
        depot, cluster, curE, node, isnewp, cmaskp, vcmp, maskp,
        Wq, Wk, Wv, Wks, Wmq, Wmk, Wmv, Wmo, (float*)d_out);
}

// round 6
// speedup vs baseline: 1.0026x; 1.0026x over previous
#include <cuda_runtime.h>
#include <math.h>

// Problem constants
#define BB 128
#define NN 2000
#define CC 100
#define DD 128
#define HH 8
#define DKK 16
#define NEGV (-1000000000.0f)
#define CLIPV 10.0f

// Output layout (float32, flattened tuple order)
// aug:      [0,        65536)   B*512
// guid_emb: [65536,    81920)   B*128
// guidance: [81920,    82048)   B
// clu_prob: [82048,    94848)   B*100
#define OUT_AUG 0
#define OUT_GEMB 65536
#define OUT_GUID 81920
#define OUT_CLU 82048

// Shared memory layout (float offsets). All float4 regions are 16B aligned.
#define S_CS 0           // cluster tile [100][129]
#define S_WB 12900       // weight stage / reduction scratch [128][129]
#define S_M1 29412       // mean1 [128]
#define S_M2 29540       // mean2 [128]
#define S_CUR 29668      // current [128]
#define S_DEP 29796      // depot [128]
#define S_CTX 29924      // context [384]
#define S_QV 30308       // q [128]
#define S_QH 30436       // qh [128]
#define S_R4 30564       // r packed [128][8]
#define S_U4 31588       // u packed [128][8]
#define S_SC 32612       // scores [8][104]
#define S_AT4 33444      // attn packed [100][8]
#define S_WS4 34244      // wsum packed [128][8]
#define S_YS 35268       // y [8][132]
#define S_GV 36324       // glimpse (pre-Wmo) [128]
#define S_GO 36452       // glimpse @ Wmo [128]
#define S_GW 36580       // Wks @ go [128]
#define S_PART 36708     // logit partials [100][2] (pad 208)
#define S_LGT 36916      // logits [104]
#define S_MISC 37020     // [0]=gid [1]=max+lse
#define S_VCM 37036      // vcm [104]
#define SMEM_FLOATS 37140
#define SMEM_BYTES (SMEM_FLOATS * 4)

__device__ __forceinline__ bool rdmask(const void* p, int flag, long long i) {
    if (flag == 0) return ((const unsigned char*)p)[i] != 0;
    if (flag == 1) return ((const int*)p)[i] != 0;
    return ((const float*)p)[i] != 0.0f;
}

// Masked-mean accumulation over node_embeddings, specialized on mask dtype.
template <int F>
__device__ __forceinline__ void means_acc(const float* __restrict__ np_,
                                          const void* __restrict__ maskp,
                                          const void* __restrict__ cmaskp,
                                          long long mbase, int w, int d0,
                                          float4& a1, float4& a2) {
#pragma unroll 5
    for (int n = w; n < NN; n += 8) {
        float4 v = *(const float4*)(np_ + (size_t)n * DD + d0);
        bool m, cmv;
        if (F == 0) {
            m = ((const unsigned char*)maskp)[mbase + n] != 0;
            cmv = ((const unsigned char*)cmaskp)[mbase + n] != 0;
        } else if (F == 1) {
            m = ((const int*)maskp)[mbase + n] != 0;
            cmv = ((const int*)cmaskp)[mbase + n] != 0;
        } else {
            m = ((const float*)maskp)[mbase + n] != 0.0f;
            cmv = ((const float*)cmaskp)[mbase + n] != 0.0f;
        }
        bool mc = m | cmv;
        if (!m)  { a1.x += v.x; a1.y += v.y; a1.z += v.z; a1.w += v.w; }
        if (!mc) { a2.x += v.x; a2.y += v.y; a2.z += v.z; a2.w += v.w; }
    }
}

__global__ void __launch_bounds__(256, 1)
clu_fused_kernel(const float* __restrict__ depot, const float* __restrict__ cluster,
                 const float* __restrict__ curE, const float* __restrict__ node,
                 const void* __restrict__ isnewp, const void* __restrict__ cmaskp,
                 const void* __restrict__ vcmp, const void* __restrict__ maskp,
                 const float* __restrict__ Wq, const float* __restrict__ Wk,
                 const float* __restrict__ Wv, const float* __restrict__ Wks,
                 const float* __restrict__ Wmq, const float* __restrict__ Wmk,
                 const float* __restrict__ Wmv, const float* __restrict__ Wmo,
                 float* __restrict__ out) {
    extern __shared__ float sm[];
    const int b = blockIdx.x;
    const int t = threadIdx.x;
    const int lane = t & 31;
    const int w = t >> 5;

    // ---- Phase 0a: sniff bool serialization dtype (byte / int32 / float32) ----
    unsigned wword = ((const unsigned*)maskp)[t];  // first 1024 bytes of `mask`
    int o1  = __syncthreads_or((wword & 0x0000ff00u) ? 1 : 0);
    int o23 = __syncthreads_or((wword & 0xffff0000u) ? 1 : 0);
    const int flag = o1 ? 0 : (o23 ? 2 : 1);

    // ---- Phase 0b: small loads (current/depot/vcm), cluster tile -> smem ----
    if (t < DD) {
        sm[S_CUR + t] = curE[b * DD + t];
        sm[S_DEP + t] = depot[b * DD + t];
    }
    if (t < CC) sm[S_VCM + t] = rdmask(vcmp, flag, (long long)b * CC + t) ? 1.0f : 0.0f;
    const bool isnew = rdmask(isnewp, flag, b);

    {
        const float* cp = cluster + (size_t)b * CC * DD;
        for (int p4 = t; p4 < (CC * DD) / 4; p4 += 256) {
            float4 v = ((const float4*)cp)[p4];
            int base = p4 * 4;
            float* dst = sm + S_CS + (base >> 7) * 129 + (base & 127);
            dst[0] = v.x; dst[1] = v.y; dst[2] = v.z; dst[3] = v.w;
        }
    }
    __syncthreads();

    // vcm[0] adjustment: all_vis over c=1..99 (warp 0)
    if (w == 0) {
        bool ok = true;
        for (int c = 1 + lane; c < CC; c += 32) ok = ok && (sm[S_VCM + c] != 0.0f);
        bool allv = __all_sync(0xffffffffu, ok);
        if (lane == 0 && isnew) sm[S_VCM + 0] = allv ? 0.0f : 1.0f;
    }

    // ---- Phase 1: masked means over node_embeddings (the HBM pass) ----
    {
        const float* np_ = node + (size_t)b * NN * DD;
        const long long mbase = (long long)b * NN;
        const int d0 = lane * 4;
        float4 a1 = make_float4(0.f, 0.f, 0.f, 0.f);
        float4 a2 = make_float4(0.f, 0.f, 0.f, 0.f);
        if (flag == 0)      means_acc<0>(np_, maskp, cmaskp, mbase, w, d0, a1, a2);
        else if (flag == 1) means_acc<1>(np_, maskp, cmaskp, mbase, w, d0, a1, a2);
        else                means_acc<2>(np_, maskp, cmaskp, mbase, w, d0, a1, a2);
        // deterministic cross-warp reduction via Wb scratch
        float* red1 = sm + S_WB;
        float* red2 = sm + S_WB + 1024;
        int o = w * 128 + d0;
        red1[o] = a1.x; red1[o + 1] = a1.y; red1[o + 2] = a1.z; red1[o + 3] = a1.w;
        red2[o] = a2.x; red2[o + 1] = a2.y; red2[o + 2] = a2.z; red2[o + 3] = a2.w;
    }
    __syncthreads();
    if (t < DD) {
        float s1 = 0.f, s2 = 0.f;
#pragma unroll
        for (int ww = 0; ww < 8; ww++) {
            s1 += sm[S_WB + ww * 128 + t];
            s2 += sm[S_WB + 1024 + ww * 128 + t];
        }
        float m1 = s1 * (1.0f / NN), m2 = s2 * (1.0f / NN);
        sm[S_M1 + t] = m1;
        sm[S_M2 + t] = m2;
        sm[S_CTX + t] = m1;
        sm[S_CTX + 128 + t] = sm[S_CUR + t];
        sm[S_CTX + 256 + t] = sm[S_DEP + t];
    }
    __syncthreads();

    // ---- Phase 2: q = ctx @ Wq ; qh = q @ Wmq ----
    if (t < DD) {
        float acc = 0.f;
#pragma unroll 8
        for (int i = 0; i < 3 * DD; i++) acc = fmaf(sm[S_CTX + i], Wq[i * DD + t], acc);
        sm[S_QV + t] = acc;
    }
    __syncthreads();
    if (t < DD) {
        float acc = 0.f;
#pragma unroll 8
        for (int j = 0; j < DD; j++) acc = fmaf(sm[S_QV + j], Wmq[j * DD + t], acc);
        sm[S_QH + t] = acc;
    }
    __syncthreads();

    // ---- Phase 3: stage Wmk; r[h][j] = sum_k Wmk[j][16h+k]*qh[16h+k] ----
    for (int p4 = t; p4 < (DD * DD) / 4; p4 += 256) {
        float4 v = ((const float4*)Wmk)[p4];
        int base = p4 * 4;
        float* dst = sm + S_WB + (base >> 7) * 129 + (base & 127);
        dst[0] = v.x; dst[1] = v.y; dst[2] = v.z; dst[3] = v.w;
    }
    __syncthreads();
    {
        int j = t & 127, par = t >> 7;
        float racc[4];
#pragma unroll
        for (int m = 0; m < 4; m++) {
            int h = par + 2 * m;
            float a = 0.f;
#pragma unroll
            for (int k = 0; k < 16; k++)
                a = fmaf(sm[S_WB + j * 129 + 16 * h + k], sm[S_QH + 16 * h + k], a);
            racc[m] = a;
        }
        float* dst = sm + S_R4 + j * 8 + par * 4;
        dst[0] = racc[0]; dst[1] = racc[1]; dst[2] = racc[2]; dst[3] = racc[3];
    }
    __syncthreads();

    // ---- Phase 4: stage Wk; u[h][i] = sum_j Wk[i][j]*r[h][j] ----
    for (int p4 = t; p4 < (DD * DD) / 4; p4 += 256) {
        float4 v = ((const float4*)Wk)[p4];
        int base = p4 * 4;
        float* dst = sm + S_WB + (base >> 7) * 129 + (base & 127);
        dst[0] = v.x; dst[1] = v.y; dst[2] = v.z; dst[3] = v.w;
    }
    __syncthreads();
    {
        int i = t & 127, par = t >> 7;
        float acc[4] = {0.f, 0.f, 0.f, 0.f};
#pragma unroll 4
        for (int j = 0; j < DD; j++) {
            float wv_ = sm[S_WB + i * 129 + j];
            float4 rv = *(const float4*)(sm + S_R4 + j * 8 + par * 4);
            acc[0] = fmaf(wv_, rv.x, acc[0]);
            acc[1] = fmaf(wv_, rv.y, acc[1]);
            acc[2] = fmaf(wv_, rv.z, acc[2]);
            acc[3] = fmaf(wv_, rv.w, acc[3]);
        }
        float* dst = sm + S_U4 + i * 8 + par * 4;
        dst[0] = acc[0]; dst[1] = acc[1]; dst[2] = acc[2]; dst[3] = acc[3];
    }
    __syncthreads();

    // ---- Phase 5: scores[c][h] = cluster[c]·u[h] * 0.25, masked ----
    if (t < 2 * CC) {
        int c = t >> 1, par = t & 1;
        float acc[4] = {0.f, 0.f, 0.f, 0.f};
#pragma unroll 4
        for (int i = 0; i < DD; i++) {
            float cv = sm[S_CS + c * 129 + i];
            float4 uu = *(const float4*)(sm + S_U4 + i * 8 + par * 4);
            acc[0] = fmaf(cv, uu.x, acc[0]);
            acc[1] = fmaf(cv, uu.y, acc[1]);
            acc[2] = fmaf(cv, uu.z, acc[2]);
            acc[3] = fmaf(cv, uu.w, acc[3]);
        }
        bool msk = sm[S_VCM + c] != 0.0f;
#pragma unroll
        for (int m = 0; m < 4; m++) {
            int h = par + 2 * m;
            sm[S_SC + h * 104 + c] = msk ? NEGV : acc[m] * 0.25f;
        }
    }
    __syncthreads();

    // ---- Phase 5b: softmax over c, per head (warp h) ----
    {
        int h = w;
        float mx = -INFINITY;
        for (int c = lane; c < CC; c += 32) mx = fmaxf(mx, sm[S_SC + h * 104 + c]);
#pragma unroll
        for (int off = 16; off; off >>= 1) mx = fmaxf(mx, __shfl_xor_sync(0xffffffffu, mx, off));
        float s = 0.f;
        for (int c = lane; c < CC; c += 32) {
            float e = expf(sm[S_SC + h * 104 + c] - mx);
            s += e;
            sm[S_AT4 + c * 8 + (h & 1) * 4 + (h >> 1)] = e;
        }
#pragma unroll
        for (int off = 16; off; off >>= 1) s += __shfl_xor_sync(0xffffffffu, s, off);
        float inv = 1.0f / s;
        for (int c = lane; c < CC; c += 32)
            sm[S_AT4 + c * 8 + (h & 1) * 4 + (h >> 1)] *= inv;
    }
    __syncthreads();

    // ---- Phase 6: wsum[h][i] = sum_c attn[h][c]*cluster[c][i] ----
    {
        int i = t & 127, par = t >> 7;
        float acc[4] = {0.f, 0.f, 0.f, 0.f};
#pragma unroll 4
        for (int c = 0; c < CC; c++) {
            float cv = sm[S_CS + c * 129 + i];
            float4 av = *(const float4*)(sm + S_AT4 + c * 8 + par * 4);
            acc[0] = fmaf(av.x, cv, acc[0]);
            acc[1] = fmaf(av.y, cv, acc[1]);
            acc[2] = fmaf(av.z, cv, acc[2]);
            acc[3] = fmaf(av.w, cv, acc[3]);
        }
        float* dst = sm + S_WS4 + i * 8 + par * 4;
        dst[0] = acc[0]; dst[1] = acc[1]; dst[2] = acc[2]; dst[3] = acc[3];
    }
    __syncthreads();

    // ---- Phase 7: y[h][j] = sum_i wsum[h][i]*Wv[i][j] ----
    {
        int j = t & 127, par = t >> 7;
        float acc[4] = {0.f, 0.f, 0.f, 0.f};
#pragma unroll 4
        for (int i = 0; i < DD; i++) {
            float wvv = Wv[i * DD + j];
            float4 sv = *(const float4*)(sm + S_WS4 + i * 8 + par * 4);
            acc[0] = fmaf(sv.x, wvv, acc[0]);
            acc[1] = fmaf(sv.y, wvv, acc[1]);
            acc[2] = fmaf(sv.z, wvv, acc[2]);
            acc[3] = fmaf(sv.w, wvv, acc[3]);
        }
#pragma unroll
        for (int m = 0; m < 4; m++) sm[S_YS + (par + 2 * m) * 132 + j] = acc[m];
    }
    __syncthreads();

    // ---- Phase 7b: glimpse[16h+k] = sum_j y[h][j]*Wmv[j][16h+k]; then @Wmo ----
    if (t < DD) {
        int h = t >> 4;
        float acc = 0.f;
#pragma unroll 8
        for (int j = 0; j < DD; j++) acc = fmaf(sm[S_YS + h * 132 + j], Wmv[j * DD + t], acc);
        sm[S_GV + t] = acc;
    }
    __syncthreads();
    if (t < DD) {
        float acc = 0.f;
#pragma unroll 8
        for (int j = 0; j < DD; j++) acc = fmaf(sm[S_GV + j], Wmo[j * DD + t], acc);
        sm[S_GO + t] = acc;
    }
    __syncthreads();

    // ---- Phase 8: stage Wks; gw[i] = sum_j Wks[i][j]*go[j]; logits ----
    for (int p4 = t; p4 < (DD * DD) / 4; p4 += 256) {
        float4 v = ((const float4*)Wks)[p4];
        int base = p4 * 4;
        float* dst = sm + S_WB + (base >> 7) * 129 + (base & 127);
        dst[0] = v.x; dst[1] = v.y; dst[2] = v.z; dst[3] = v.w;
    }
    __syncthreads();
    if (t < DD) {
        float acc = 0.f;
#pragma unroll 8
        for (int j = 0; j < DD; j++) acc = fmaf(sm[S_WB + t * 129 + j], sm[S_GO + j], acc);
        sm[S_GW + t] = acc;
    }
    __syncthreads();
    if (t < 2 * CC) {
        int c = t >> 1, half = t & 1;
        float acc = 0.f;
        int i0 = half * 64;
#pragma unroll 8
        for (int i = i0; i < i0 + 64; i++)
            acc = fmaf(sm[S_CS + c * 129 + i], sm[S_GW + i], acc);
        sm[S_PART + c * 2 + half] = acc;
    }
    __syncthreads();
    if (t < CC) {
        float lg = (sm[S_PART + t * 2] + sm[S_PART + t * 2 + 1]) * 0.08838834764831845f;
        lg = tanhf(lg) * CLIPV;
        sm[S_LGT + t] = (sm[S_VCM + t] != 0.0f) ? NEGV : lg;
    }
    __syncthreads();

    // ---- Phase 8b: argmax (first-index ties) + logsumexp (warp 0) ----
    if (w == 0) {
        float bv = -INFINITY;
        int bi = 0x7fffffff;
        for (int c = lane; c < CC; c += 32) {
            float v = sm[S_LGT + c];
            if (v > bv || (v == bv && c < bi)) { bv = v; bi = c; }
        }
#pragma unroll
        for (int off = 16; off; off >>= 1) {
            float ov = __shfl_down_sync(0xffffffffu, bv, off);
            int oi = __shfl_down_sync(0xffffffffu, bi, off);
            if (ov > bv || (ov == bv && oi < bi)) { bv = ov; bi = oi; }
        }
        bv = __shfl_sync(0xffffffffu, bv, 0);
        bi = __shfl_sync(0xffffffffu, bi, 0);
        float s = 0.f;
        for (int c = lane; c < CC; c += 32) s += expf(sm[S_LGT + c] - bv);
#pragma unroll
        for (int off = 16; off; off >>= 1) s += __shfl_xor_sync(0xffffffffu, s, off);
        if (lane == 0) {
            sm[S_MISC + 0] = (float)bi;
            sm[S_MISC + 1] = bv + logf(s);
        }
    }
    __syncthreads();

    // ---- Phase 9: outputs ----
    const int gid = (int)sm[S_MISC + 0];
    const float mlse = sm[S_MISC + 1];
    float* aug = out + OUT_AUG + (size_t)b * 512;
    float* gout = out + OUT_GEMB + (size_t)b * 128;
    float* cpo = out + OUT_CLU + (size_t)b * CC;
    if (t < DD) {
        float ge = sm[S_CS + gid * 129 + t];
        aug[t]        = isnew ? sm[S_M2 + t] : 0.0f;
        aug[128 + t]  = isnew ? sm[S_CUR + t] : 0.0f;
        aug[256 + t]  = isnew ? ge : 0.0f;
        aug[384 + t]  = isnew ? sm[S_DEP + t] : 0.0f;
        gout[t]       = isnew ? ge : 0.0f;
    }
    if (t < CC) cpo[t] = isnew ? (sm[S_LGT + t] - mlse) : 0.0f;
    if (t == 0) out[OUT_GUID + b] = isnew ? (float)gid : 0.0f;
}

extern "C" void kernel_launch(void* const* d_in, const int* in_sizes, int n_in,
                              void* d_out, int out_size) {
    (void)in_sizes; (void)n_in; (void)out_size;
    const float* depot   = (const float*)d_in[0];
    const float* cluster = (const float*)d_in[1];
    const float* curE    = (const float*)d_in[2];
    const float* node    = (const float*)d_in[3];
    const void*  isnewp  = d_in[4];
    const void*  cmaskp  = d_in[5];
    const void*  vcmp    = d_in[6];
    const void*  maskp   = d_in[7];
    const float* Wq  = (const float*)d_in[8];
    const float* Wk  = (const float*)d_in[9];
    const float* Wv  = (const float*)d_in[10];
    const float* Wks = (const float*)d_in[11];
    const float* Wmq = (const float*)d_in[12];
    const float* Wmk = (const float*)d_in[13];
    const float* Wmv = (const float*)d_in[14];
    const float* Wmo = (const float*)d_in[15];

    cudaFuncSetAttribute(clu_fused_kernel,
                         cudaFuncAttributeMaxDynamicSharedMemorySize, SMEM_BYTES);
    clu_fused_kernel<<<BB, 256, SMEM_BYTES>>>(
        depot, cluster, curE, node, isnewp, cmaskp, vcmp, maskp,
        Wq, Wk, Wv, Wks, Wmq, Wmk, Wmv, Wmo, (float*)d_out);
}